// round 16
// baseline (speedup 1.0000x reference)
#include <cuda_runtime.h>
#include <cuda_fp16.h>
#include <math.h>
#include <stdint.h>

#define TSEQ   2048
#define NH     16
#define DLORA  512
// SCALE * log2(e)
#define QS      0.1041277131f
#define MASKVAL (-30000.f)

// ---------------- scratch (device globals; allocation-free) ----------------
__device__ __half g_kc_h[TSEQ * DLORA];          // [t][l]
__device__ __half g_wt_h[4096 * DLORA];          // [n][l] combined weight^T
__device__ __half g_ksp[TSEQ * NH * 192];        // [t][h][ nope(128)|rope(64) ]
__device__ __half g_vt[NH * 128 * TSEQ];         // [h][dv][t]
__device__ int    g_job;                         // attn work-queue counter

// ---------------- helpers ----------------
__device__ __forceinline__ uint32_t smem_u32(const void* p) {
    uint32_t a;
    asm("{ .reg .u64 t; cvta.to.shared.u64 t, %1; cvt.u32.u64 %0, t; }" : "=r"(a) : "l"(p));
    return a;
}
__device__ __forceinline__ uint32_t pack2(float a, float b) {
    __half2 h = __floats2half2_rn(a, b);
    return *reinterpret_cast<uint32_t*>(&h);
}
__device__ __forceinline__ uint32_t hexp2(uint32_t h) {
    uint32_t r;
    asm("ex2.approx.f16x2 %0, %1;" : "=r"(r) : "r"(h));
    return r;
}
__device__ __forceinline__ void ldsm4(uint32_t a, uint32_t& r0, uint32_t& r1, uint32_t& r2, uint32_t& r3) {
    asm volatile("ldmatrix.sync.aligned.m8n8.x4.shared.b16 {%0,%1,%2,%3}, [%4];"
                 : "=r"(r0), "=r"(r1), "=r"(r2), "=r"(r3) : "r"(a));
}
__device__ __forceinline__ void mma16816(float* c, uint32_t a0, uint32_t a1, uint32_t a2, uint32_t a3,
                                         uint32_t b0, uint32_t b1) {
    asm volatile("mma.sync.aligned.m16n8k16.row.col.f32.f16.f16.f32 "
                 "{%0,%1,%2,%3}, {%4,%5,%6,%7}, {%8,%9}, {%0,%1,%2,%3};"
                 : "+f"(c[0]), "+f"(c[1]), "+f"(c[2]), "+f"(c[3])
                 : "r"(a0), "r"(a1), "r"(a2), "r"(a3), "r"(b0), "r"(b1));
}
__device__ __forceinline__ uint32_t lmaddr(uint32_t base, int row0, int pitch, int col0, int lane) {
    return base + (uint32_t)(((row0 + (lane & 15)) * pitch + col0 + ((lane >> 4) << 3)) * 2);
}
__device__ __forceinline__ void cp16(uint32_t d, const void* s) {
    asm volatile("cp.async.cg.shared.global [%0], [%1], 16;" :: "r"(d), "l"(s));
}
#define CP_COMMIT() asm volatile("cp.async.commit_group;" ::: "memory")
#define CP_WAIT0()  asm volatile("cp.async.wait_group 0;" ::: "memory")
#define CP_WAIT1()  asm volatile("cp.async.wait_group 1;" ::: "memory")

// ---------------- fused converter (one launch) ----------------
__global__ __launch_bounds__(256) void conv_all(const float* __restrict__ wkv,
                                                const float* __restrict__ wuv,
                                                const float* __restrict__ kc,
                                                const float* __restrict__ kpe) {
    const int bid = blockIdx.x, tid = threadIdx.x;
    if (bid < 512) {
        __shared__ __half sW[32][130];
        const int nt = bid & 31;
        const int lt = bid >> 5;
        const bool isW = nt < 16;
#pragma unroll
        for (int it = 0; it < 16; it++) {
            int idx = tid + it * 256;
            int nl = idx & 127, ll = idx >> 7;
            int l = lt * 32 + ll;
            float x;
            if (isW) x = wkv[(size_t)l * 4096 + nt * 256 + nl];
            else     x = wuv[(size_t)(nt - 16) * 65536 + (size_t)l * 128 + nl];
            sW[ll][nl] = __float2half_rn(x);
        }
        __syncthreads();
        int ll = tid & 31;
        int n0 = (tid >> 5) * 16;
#pragma unroll
        for (int i = 0; i < 16; i++) {
            int n = n0 + i;
            g_wt_h[(size_t)(nt * 128 + n) * 512 + lt * 32 + ll] = sW[ll][n];
        }
    } else {
        int i = (bid - 512) * 256 + tid;
        if (i == 0) g_job = 0;
        if (i < TSEQ * DLORA / 4) {
            float4 v = *(const float4*)(kc + (size_t)i * 4);
            *(uint2*)(g_kc_h + (size_t)i * 4) = make_uint2(pack2(v.x, v.y), pack2(v.z, v.w));
        }
        {
            int t = i >> 9, h = (i >> 5) & 15, d2 = i & 31;
            float2 v = *(const float2*)(kpe + t * 64 + d2 * 2);
            *(uint32_t*)(g_ksp + (size_t)(t * 16 + h) * 192 + 128 + d2 * 2) = pack2(v.x, v.y);
        }
    }
}

// ---------------- pre-GEMM: D = kc_hi @ W_hi^T, k=64 chunks double-buffered -------
#define PG_SMEM 73728
__global__ __launch_bounds__(256, 2) void pregemm() {
    extern __shared__ __align__(16) __half smh[];
    float* sT = (float*)smh;
    const uint32_t sb = smem_u32(smh);
    const int nt = blockIdx.x, mt = blockIdx.y;
    const int tid = threadIdx.x, lane = tid & 31, w = tid >> 5;
    const int wm = w >> 2, wn = w & 3;
    const int g = lane >> 2, t2 = lane & 3;

    float acc[4][4][4];
#pragma unroll
    for (int a = 0; a < 4; a++)
#pragma unroll
        for (int b = 0; b < 4; b++)
#pragma unroll
            for (int c = 0; c < 4; c++) acc[a][b][c] = 0.f;

    auto prefetch = [&](int chunk, int buf) {
        const int kk = chunk * 64;
        uint32_t ab = sb + (uint32_t)buf * 18432u * 2;
        uint32_t bb = ab + 9216u * 2;
#pragma unroll
        for (int it = 0; it < 4; it++) {
            int idx = tid + it * 256;
            int r = idx >> 3, c8 = idx & 7;
            uint32_t off = (uint32_t)(r * 72 + c8 * 8) * 2;
            cp16(ab + off, g_kc_h + (size_t)(mt * 128 + r) * 512 + kk + c8 * 8);
            cp16(bb + off, g_wt_h + (size_t)(nt * 128 + r) * 512 + kk + c8 * 8);
        }
    };

    prefetch(0, 0); CP_COMMIT();
    for (int chunk = 0; chunk < 8; chunk++) {
        if (chunk < 7) { prefetch(chunk + 1, (chunk + 1) & 1); CP_COMMIT(); CP_WAIT1(); }
        else           { CP_WAIT0(); }
        __syncthreads();
        uint32_t ab = sb + (uint32_t)(chunk & 1) * 18432u * 2;
        uint32_t bb = ab + 9216u * 2;
#pragma unroll
        for (int ks = 0; ks < 4; ks++) {
            uint32_t af[4][4];
#pragma unroll
            for (int mf = 0; mf < 4; mf++)
                ldsm4(lmaddr(ab, wm * 64 + mf * 16, 72, ks * 16, lane),
                      af[mf][0], af[mf][1], af[mf][2], af[mf][3]);
#pragma unroll
            for (int ng = 0; ng < 2; ng++) {
                uint32_t b0, b1, b2, b3;
                ldsm4(lmaddr(bb, wn * 32 + ng * 16, 72, ks * 16, lane), b0, b1, b2, b3);
#pragma unroll
                for (int mf = 0; mf < 4; mf++) {
                    mma16816(acc[mf][2 * ng],     af[mf][0], af[mf][1], af[mf][2], af[mf][3], b0, b2);
                    mma16816(acc[mf][2 * ng + 1], af[mf][0], af[mf][1], af[mf][2], af[mf][3], b1, b3);
                }
            }
        }
        __syncthreads();
    }

#pragma unroll
    for (int mf = 0; mf < 4; mf++)
#pragma unroll
        for (int nf = 0; nf < 4; nf++) {
            int rr = wm * 64 + mf * 16 + g, cc = wn * 32 + nf * 8 + 2 * t2;
            sT[rr * 129 + cc]       = acc[mf][nf][0];
            sT[rr * 129 + cc + 1]   = acc[mf][nf][1];
            sT[(rr + 8) * 129 + cc]     = acc[mf][nf][2];
            sT[(rr + 8) * 129 + cc + 1] = acc[mf][nf][3];
        }
    __syncthreads();

    if (tid < 128) {
        if (nt < 16) {
            size_t base = (size_t)((mt * 128 + tid) * 16 + nt) * 192;
#pragma unroll
            for (int ch = 0; ch < 4; ch++) {
                uint32_t hh[16];
#pragma unroll
                for (int i = 0; i < 16; i++)
                    hh[i] = pack2(sT[tid * 129 + ch * 32 + 2 * i], sT[tid * 129 + ch * 32 + 2 * i + 1]);
#pragma unroll
                for (int k = 0; k < 4; k++)
                    *(uint4*)(g_ksp + base + ch * 32 + k * 8) = make_uint4(hh[4*k], hh[4*k+1], hh[4*k+2], hh[4*k+3]);
            }
        } else {
            int h = nt - 16;
            size_t base = (size_t)(h * 128 + tid) * 2048 + mt * 128;
#pragma unroll
            for (int ch = 0; ch < 4; ch++) {
                uint32_t hh[16];
#pragma unroll
                for (int i = 0; i < 16; i++)
                    hh[i] = pack2(sT[(ch * 32 + 2 * i) * 129 + tid], sT[(ch * 32 + 2 * i + 1) * 129 + tid]);
#pragma unroll
                for (int k = 0; k < 4; k++)
                    *(uint4*)(g_vt + base + ch * 32 + k * 8) = make_uint4(hh[4*k], hh[4*k+1], hh[4*k+2], hh[4*k+3]);
            }
        }
    }
}

// ---------------- attention: split-K, 256 thr (4 m-groups x 2 key-halves), 2 CTA/SM
// smem halves: K0:0 (64x200=12800) | K1:12800 | Q:25600 (64x200) | V0:38400 (128x72)
//              | V1:47616 | EXCH(float):56832h  -> total 114176 B
// Epilogue sO: float [64][130] aliasing K0+K1 (33280 B <= 51200 B, loop finished).
#define AT_SMEM 114176
#define NJOBS   512
__global__ __launch_bounds__(256, 2) void attn(const float* __restrict__ q, float* __restrict__ out) {
    extern __shared__ __align__(16) __half smh[];
    __shared__ int s_job;
    const uint32_t sb = smem_u32(smh);
    const uint32_t sQb = sb + 25600u * 2;
    float* exch = (float*)(smh + 56832);
    float* sO   = (float*)smh;                       // K0+K1 region, epilogue only
    const int tid = threadIdx.x, lane = tid & 31, w = tid >> 5;
    const int wm = w >> 1, wn = w & 1;
    const int m0 = wm * 16, g = lane >> 2, t2 = lane & 3;
    const int n0 = wn * 32;

    for (;;) {
        if (tid == 0) s_job = atomicAdd(&g_job, 1);
        __syncthreads();
        const int job = s_job;
        if (job >= NJOBS) break;
        const int qt = 31 - (job >> 4), h = job & 15;     // LPT order
        const int gr0 = qt * 64 + m0 + g, gr1 = gr0 + 8;
        const int jmax = qt;

        // stage Q (prescaled by SCALE*log2e)
        for (int idx = tid; idx < 64 * 48; idx += 256) {
            int r = idx / 48, c = idx % 48;
            float4 v = *(const float4*)(q + (size_t)((qt * 64 + r) * 16 + h) * 192 + c * 4);
            *(uint2*)(smh + 25600 + r * 200 + c * 4) =
                make_uint2(pack2(v.x * QS, v.y * QS), pack2(v.z * QS, v.w * QS));
        }

        auto prefetch = [&](int j, int buf) {
            uint32_t kb = sb + (uint32_t)buf * 12800u * 2;
            uint32_t vb = sb + (38400u + (uint32_t)buf * 9216u) * 2;
#pragma unroll
            for (int it = 0; it < 6; it++) {
                int idx = tid + it * 256;
                int r = idx / 24, c = idx % 24;
                cp16(kb + (uint32_t)(r * 200 + c * 8) * 2,
                     g_ksp + (size_t)((j * 64 + r) * 16 + h) * 192 + c * 8);
            }
#pragma unroll
            for (int it = 0; it < 4; it++) {
                int idx = tid + it * 256;
                int r = idx >> 3, c = idx & 7;
                cp16(vb + (uint32_t)(r * 72 + c * 8) * 2,
                     g_vt + (size_t)(h * 128 + r) * 2048 + j * 64 + c * 8);
            }
        };

        prefetch(0, 0); CP_COMMIT();

        float O[16][4];
#pragma unroll
        for (int f = 0; f < 16; f++)
#pragma unroll
            for (int c = 0; c < 4; c++) O[f][c] = 0.f;
        float mr0 = -INFINITY, mr1 = -INFINITY, sr0 = 0.f, sr1 = 0.f;

        for (int j = 0; j <= jmax; j++) {
            CP_WAIT0();
            __syncthreads();                              // barrier 1: tile start
            if (j < jmax) { prefetch(j + 1, (j + 1) & 1); CP_COMMIT(); }
            const uint32_t sKb = sb + (uint32_t)(j & 1) * 12800u * 2;
            const uint32_t sVb = sb + (38400u + (uint32_t)(j & 1) * 9216u) * 2;

            // S = Q @ K^T (this warp's 32 keys)
            float Sc[4][4];
#pragma unroll
            for (int f = 0; f < 4; f++)
#pragma unroll
                for (int c = 0; c < 4; c++) Sc[f][c] = 0.f;
#pragma unroll
            for (int kk = 0; kk < 12; kk++) {
                uint32_t a0, a1, a2, a3;
                ldsm4(lmaddr(sQb, m0, 200, kk * 16, lane), a0, a1, a2, a3);
#pragma unroll
                for (int nf2 = 0; nf2 < 2; nf2++) {
                    uint32_t b0, b1, b2, b3;
                    ldsm4(lmaddr(sKb, n0 + nf2 * 16, 200, kk * 16, lane), b0, b1, b2, b3);
                    mma16816(Sc[2 * nf2],     a0, a1, a2, a3, b0, b2);
                    mma16816(Sc[2 * nf2 + 1], a0, a1, a2, a3, b1, b3);
                }
            }

            // diagonal mask
            if (j == jmax) {
#pragma unroll
                for (int f = 0; f < 4; f++) {
                    int c0 = j * 64 + n0 + f * 8 + t2 * 2;
                    Sc[f][0] = (c0     <= gr0) ? Sc[f][0] : MASKVAL;
                    Sc[f][1] = (c0 + 1 <= gr0) ? Sc[f][1] : MASKVAL;
                    Sc[f][2] = (c0     <= gr1) ? Sc[f][2] : MASKVAL;
                    Sc[f][3] = (c0 + 1 <= gr1) ? Sc[f][3] : MASKVAL;
                }
            }
            // local row max over 32 keys
            float mx0 = -INFINITY, mx1 = -INFINITY;
#pragma unroll
            for (int f = 0; f < 4; f++) {
                mx0 = fmaxf(mx0, fmaxf(Sc[f][0], Sc[f][1]));
                mx1 = fmaxf(mx1, fmaxf(Sc[f][2], Sc[f][3]));
            }
            mx0 = fmaxf(mx0, __shfl_xor_sync(0xffffffffu, mx0, 1));
            mx0 = fmaxf(mx0, __shfl_xor_sync(0xffffffffu, mx0, 2));
            mx1 = fmaxf(mx1, __shfl_xor_sync(0xffffffffu, mx1, 1));
            mx1 = fmaxf(mx1, __shfl_xor_sync(0xffffffffu, mx1, 2));
            // cross-warp (pair) max exchange
            if (t2 == 0) { exch[w * 16 + g] = mx0; exch[w * 16 + 8 + g] = mx1; }
            __syncthreads();                              // barrier 2
            mx0 = fmaxf(mx0, exch[(w ^ 1) * 16 + g]);
            mx1 = fmaxf(mx1, exch[(w ^ 1) * 16 + 8 + g]);
            float mn0 = fmaxf(mr0, mx0), mn1 = fmaxf(mr1, mx1);
            float al0 = exp2f(mr0 - mn0), al1 = exp2f(mr1 - mn1);
            mr0 = mn0; mr1 = mn1;

            if (!__all_sync(0xffffffffu, (al0 == 1.f) & (al1 == 1.f))) {
#pragma unroll
                for (int f = 0; f < 16; f++) {
                    O[f][0] *= al0; O[f][1] *= al0; O[f][2] *= al1; O[f][3] *= al1;
                }
                sr0 *= al0; sr1 *= al1;
            }

            // P = 2^(S-mn), fp32 partial sums, fp16 pack
            float rs0 = 0.f, rs1 = 0.f;
            uint32_t Pa[4], Pb[4];
#pragma unroll
            for (int f = 0; f < 4; f++) {
                float e0 = exp2f(Sc[f][0] - mn0), e1 = exp2f(Sc[f][1] - mn0);
                float e2 = exp2f(Sc[f][2] - mn1), e3 = exp2f(Sc[f][3] - mn1);
                rs0 += e0 + e1; rs1 += e2 + e3;
                Pa[f] = hexp2(pack2(Sc[f][0] - mn0, Sc[f][1] - mn0));
                Pb[f] = hexp2(pack2(Sc[f][2] - mn1, Sc[f][3] - mn1));
            }
            rs0 += __shfl_xor_sync(0xffffffffu, rs0, 1);
            rs0 += __shfl_xor_sync(0xffffffffu, rs0, 2);
            rs1 += __shfl_xor_sync(0xffffffffu, rs1, 1);
            rs1 += __shfl_xor_sync(0xffffffffu, rs1, 2);
            sr0 += rs0; sr1 += rs1;

            // O += P @ V (this warp's 32 keys)
#pragma unroll
            for (int kc2 = 0; kc2 < 2; kc2++) {
                uint32_t a0 = Pa[2 * kc2], a1 = Pb[2 * kc2], a2 = Pa[2 * kc2 + 1], a3 = Pb[2 * kc2 + 1];
#pragma unroll
                for (int nf2 = 0; nf2 < 8; nf2++) {
                    uint32_t b0, b1, b2, b3;
                    ldsm4(lmaddr(sVb, nf2 * 16, 72, n0 + kc2 * 16, lane), b0, b1, b2, b3);
                    mma16816(O[2 * nf2],     a0, a1, a2, a3, b0, b2);
                    mma16816(O[2 * nf2 + 1], a0, a1, a2, a3, b1, b3);
                }
            }
        }

        // ---- epilogue: merge warp pairs (wn 0/1 hold same rows, different keys) ----
        __syncthreads();
        if (wn == 1) {
#pragma unroll
            for (int f = 0; f < 16; f++) {
                int rr = m0 + g, cc = f * 8 + t2 * 2;
                sO[rr * 130 + cc]       = O[f][0];
                sO[rr * 130 + cc + 1]   = O[f][1];
                sO[(rr + 8) * 130 + cc]     = O[f][2];
                sO[(rr + 8) * 130 + cc + 1] = O[f][3];
            }
            if (t2 == 0) { exch[w * 16 + g] = sr0; exch[w * 16 + 8 + g] = sr1; }
        }
        __syncthreads();
        if (wn == 0) {
            float inv0 = 1.f / (sr0 + exch[(w + 1) * 16 + g]);
            float inv1 = 1.f / (sr1 + exch[(w + 1) * 16 + 8 + g]);
#pragma unroll
            for (int f = 0; f < 16; f++) {
                int rr = m0 + g, cc = f * 8 + t2 * 2;
                int col = h * 128 + cc;
                *(float2*)(out + (size_t)gr0 * 2048 + col) =
                    make_float2((O[f][0] + sO[rr * 130 + cc]) * inv0,
                                (O[f][1] + sO[rr * 130 + cc + 1]) * inv0);
                *(float2*)(out + (size_t)gr1 * 2048 + col) =
                    make_float2((O[f][2] + sO[(rr + 8) * 130 + cc]) * inv1,
                                (O[f][3] + sO[(rr + 8) * 130 + cc + 1]) * inv1);
            }
        }
        __syncthreads();
    }
}

// ---------------------------------------------------------------------------
extern "C" void kernel_launch(void* const* d_in, const int* in_sizes, int n_in,
                              void* d_out, int out_size) {
    (void)in_sizes; (void)n_in; (void)out_size;
    const float* q   = (const float*)d_in[0];
    const float* kc  = (const float*)d_in[1];
    const float* kpe = (const float*)d_in[2];
    const float* wkv = (const float*)d_in[3];
    const float* wuv = (const float*)d_in[4];
    float* out = (float*)d_out;

    conv_all<<<4608, 256>>>(wkv, wuv, kc, kpe);

    cudaFuncSetAttribute(pregemm, cudaFuncAttributeMaxDynamicSharedMemorySize, PG_SMEM);
    cudaFuncSetAttribute(attn,    cudaFuncAttributeMaxDynamicSharedMemorySize, AT_SMEM);

    pregemm<<<dim3(32, 16), 256, PG_SMEM>>>();
    attn<<<296, 256, AT_SMEM>>>(q, out);
}

// round 17
// speedup vs baseline: 1.6347x; 1.6347x over previous
#include <cuda_runtime.h>
#include <cuda_fp16.h>
#include <math.h>
#include <stdint.h>

#define TSEQ   2048
#define NH     16
#define DLORA  512
// SCALE * log2(e)
#define QS      0.1041277131f
#define MASKVAL (-30000.f)

// ---------------- scratch (device globals; allocation-free) ----------------
__device__ __half g_kc_h[TSEQ * DLORA];          // [t][l]
__device__ __half g_wt_h[4096 * DLORA];          // [n][l] combined weight^T
__device__ __half g_ksp[TSEQ * NH * 192];        // [t][h][ nope(128)|rope(64) ]
__device__ __half g_vt[NH * 128 * TSEQ];         // [h][dv][t]
__device__ int    g_job;                         // attn work-queue counter

// ---------------- helpers ----------------
__device__ __forceinline__ uint32_t smem_u32(const void* p) {
    uint32_t a;
    asm("{ .reg .u64 t; cvta.to.shared.u64 t, %1; cvt.u32.u64 %0, t; }" : "=r"(a) : "l"(p));
    return a;
}
__device__ __forceinline__ uint32_t pack2(float a, float b) {
    __half2 h = __floats2half2_rn(a, b);
    return *reinterpret_cast<uint32_t*>(&h);
}
__device__ __forceinline__ uint32_t hexp2(uint32_t h) {
    uint32_t r;
    asm("ex2.approx.f16x2 %0, %1;" : "=r"(r) : "r"(h));
    return r;
}
__device__ __forceinline__ void ldsm4(uint32_t a, uint32_t& r0, uint32_t& r1, uint32_t& r2, uint32_t& r3) {
    asm volatile("ldmatrix.sync.aligned.m8n8.x4.shared.b16 {%0,%1,%2,%3}, [%4];"
                 : "=r"(r0), "=r"(r1), "=r"(r2), "=r"(r3) : "r"(a));
}
__device__ __forceinline__ void mma16816(float* c, uint32_t a0, uint32_t a1, uint32_t a2, uint32_t a3,
                                         uint32_t b0, uint32_t b1) {
    asm volatile("mma.sync.aligned.m16n8k16.row.col.f32.f16.f16.f32 "
                 "{%0,%1,%2,%3}, {%4,%5,%6,%7}, {%8,%9}, {%0,%1,%2,%3};"
                 : "+f"(c[0]), "+f"(c[1]), "+f"(c[2]), "+f"(c[3])
                 : "r"(a0), "r"(a1), "r"(a2), "r"(a3), "r"(b0), "r"(b1));
}
__device__ __forceinline__ uint32_t lmaddr(uint32_t base, int row0, int pitch, int col0, int lane) {
    return base + (uint32_t)(((row0 + (lane & 15)) * pitch + col0 + ((lane >> 4) << 3)) * 2);
}
__device__ __forceinline__ void cp16(uint32_t d, const void* s) {
    asm volatile("cp.async.cg.shared.global [%0], [%1], 16;" :: "r"(d), "l"(s));
}
#define CP_COMMIT() asm volatile("cp.async.commit_group;" ::: "memory")
#define CP_WAIT0()  asm volatile("cp.async.wait_group 0;" ::: "memory")
#define CP_WAIT1()  asm volatile("cp.async.wait_group 1;" ::: "memory")

// ---------------- fused converter (one launch) ----------------
__global__ __launch_bounds__(256) void conv_all(const float* __restrict__ wkv,
                                                const float* __restrict__ wuv,
                                                const float* __restrict__ kc,
                                                const float* __restrict__ kpe) {
    const int bid = blockIdx.x, tid = threadIdx.x;
    if (bid < 512) {
        __shared__ __half sW[32][130];
        const int nt = bid & 31;
        const int lt = bid >> 5;
        const bool isW = nt < 16;
#pragma unroll
        for (int it = 0; it < 16; it++) {
            int idx = tid + it * 256;
            int nl = idx & 127, ll = idx >> 7;
            int l = lt * 32 + ll;
            float x;
            if (isW) x = wkv[(size_t)l * 4096 + nt * 256 + nl];
            else     x = wuv[(size_t)(nt - 16) * 65536 + (size_t)l * 128 + nl];
            sW[ll][nl] = __float2half_rn(x);
        }
        __syncthreads();
        int ll = tid & 31;
        int n0 = (tid >> 5) * 16;
#pragma unroll
        for (int i = 0; i < 16; i++) {
            int n = n0 + i;
            g_wt_h[(size_t)(nt * 128 + n) * 512 + lt * 32 + ll] = sW[ll][n];
        }
    } else {
        int i = (bid - 512) * 256 + tid;
        if (i == 0) g_job = 0;
        if (i < TSEQ * DLORA / 4) {
            float4 v = *(const float4*)(kc + (size_t)i * 4);
            *(uint2*)(g_kc_h + (size_t)i * 4) = make_uint2(pack2(v.x, v.y), pack2(v.z, v.w));
        }
        {
            int t = i >> 9, h = (i >> 5) & 15, d2 = i & 31;
            float2 v = *(const float2*)(kpe + t * 64 + d2 * 2);
            *(uint32_t*)(g_ksp + (size_t)(t * 16 + h) * 192 + 128 + d2 * 2) = pack2(v.x, v.y);
        }
    }
}

// ---------------- pre-GEMM: D = kc_hi @ W_hi^T, k=64 chunks double-buffered -------
#define PG_SMEM 73728
__global__ __launch_bounds__(256, 2) void pregemm() {
    extern __shared__ __align__(16) __half smh[];
    float* sT = (float*)smh;
    const uint32_t sb = smem_u32(smh);
    const int nt = blockIdx.x, mt = blockIdx.y;
    const int tid = threadIdx.x, lane = tid & 31, w = tid >> 5;
    const int wm = w >> 2, wn = w & 3;
    const int g = lane >> 2, t2 = lane & 3;

    float acc[4][4][4];
#pragma unroll
    for (int a = 0; a < 4; a++)
#pragma unroll
        for (int b = 0; b < 4; b++)
#pragma unroll
            for (int c = 0; c < 4; c++) acc[a][b][c] = 0.f;

    auto prefetch = [&](int chunk, int buf) {
        const int kk = chunk * 64;
        uint32_t ab = sb + (uint32_t)buf * 18432u * 2;
        uint32_t bb = ab + 9216u * 2;
#pragma unroll
        for (int it = 0; it < 4; it++) {
            int idx = tid + it * 256;
            int r = idx >> 3, c8 = idx & 7;
            uint32_t off = (uint32_t)(r * 72 + c8 * 8) * 2;
            cp16(ab + off, g_kc_h + (size_t)(mt * 128 + r) * 512 + kk + c8 * 8);
            cp16(bb + off, g_wt_h + (size_t)(nt * 128 + r) * 512 + kk + c8 * 8);
        }
    };

    prefetch(0, 0); CP_COMMIT();
    for (int chunk = 0; chunk < 8; chunk++) {
        if (chunk < 7) { prefetch(chunk + 1, (chunk + 1) & 1); CP_COMMIT(); CP_WAIT1(); }
        else           { CP_WAIT0(); }
        __syncthreads();
        uint32_t ab = sb + (uint32_t)(chunk & 1) * 18432u * 2;
        uint32_t bb = ab + 9216u * 2;
#pragma unroll
        for (int ks = 0; ks < 4; ks++) {
            uint32_t af[4][4];
#pragma unroll
            for (int mf = 0; mf < 4; mf++)
                ldsm4(lmaddr(ab, wm * 64 + mf * 16, 72, ks * 16, lane),
                      af[mf][0], af[mf][1], af[mf][2], af[mf][3]);
#pragma unroll
            for (int ng = 0; ng < 2; ng++) {
                uint32_t b0, b1, b2, b3;
                ldsm4(lmaddr(bb, wn * 32 + ng * 16, 72, ks * 16, lane), b0, b1, b2, b3);
#pragma unroll
                for (int mf = 0; mf < 4; mf++) {
                    mma16816(acc[mf][2 * ng],     af[mf][0], af[mf][1], af[mf][2], af[mf][3], b0, b2);
                    mma16816(acc[mf][2 * ng + 1], af[mf][0], af[mf][1], af[mf][2], af[mf][3], b1, b3);
                }
            }
        }
        __syncthreads();
    }

#pragma unroll
    for (int mf = 0; mf < 4; mf++)
#pragma unroll
        for (int nf = 0; nf < 4; nf++) {
            int rr = wm * 64 + mf * 16 + g, cc = wn * 32 + nf * 8 + 2 * t2;
            sT[rr * 129 + cc]       = acc[mf][nf][0];
            sT[rr * 129 + cc + 1]   = acc[mf][nf][1];
            sT[(rr + 8) * 129 + cc]     = acc[mf][nf][2];
            sT[(rr + 8) * 129 + cc + 1] = acc[mf][nf][3];
        }
    __syncthreads();

    if (tid < 128) {
        if (nt < 16) {
            size_t base = (size_t)((mt * 128 + tid) * 16 + nt) * 192;
#pragma unroll
            for (int ch = 0; ch < 4; ch++) {
                uint32_t hh[16];
#pragma unroll
                for (int i = 0; i < 16; i++)
                    hh[i] = pack2(sT[tid * 129 + ch * 32 + 2 * i], sT[tid * 129 + ch * 32 + 2 * i + 1]);
#pragma unroll
                for (int k = 0; k < 4; k++)
                    *(uint4*)(g_ksp + base + ch * 32 + k * 8) = make_uint4(hh[4*k], hh[4*k+1], hh[4*k+2], hh[4*k+3]);
            }
        } else {
            int h = nt - 16;
            size_t base = (size_t)(h * 128 + tid) * 2048 + mt * 128;
#pragma unroll
            for (int ch = 0; ch < 4; ch++) {
                uint32_t hh[16];
#pragma unroll
                for (int i = 0; i < 16; i++)
                    hh[i] = pack2(sT[(ch * 32 + 2 * i) * 129 + tid], sT[(ch * 32 + 2 * i + 1) * 129 + tid]);
#pragma unroll
                for (int k = 0; k < 4; k++)
                    *(uint4*)(g_vt + base + ch * 32 + k * 8) = make_uint4(hh[4*k], hh[4*k+1], hh[4*k+2], hh[4*k+3]);
            }
        }
    }
}

// ---------------- attention: persistent work-queue, 64-key tiles, 2 CTA/SM -----
// smem (halfs): K0:0 (64x200) | K1:12800 | V0:25600 (144x72) | V1:35968 = 92672 B
#define AT_SMEM 92672
#define NJOBS   512
__global__ __launch_bounds__(128, 2) void attn(const float* __restrict__ q, float* __restrict__ out) {
    extern __shared__ __align__(16) __half smh[];
    __shared__ int s_job;
    const uint32_t sb = smem_u32(smh);
    const int tid = threadIdx.x, lane = tid & 31, w = tid >> 5;
    const int m0 = w * 16, g = lane >> 2, t2 = lane & 3;

    // ones rows (128..135) of both V buffers (persist across jobs)
    for (int idx = tid; idx < 2 * 8 * 72; idx += 128) {
        int b = idx / (8 * 72), rem = idx % (8 * 72);
        int r = rem / 72, c = rem % 72;
        smh[25600 + b * 10368 + (128 + r) * 72 + c] =
            (r == 0 && c < 64) ? __float2half(1.f) : __float2half(0.f);
    }

    for (;;) {
        if (tid == 0) s_job = atomicAdd(&g_job, 1);
        __syncthreads();
        const int job = s_job;
        if (job >= NJOBS) break;
        // LPT order: big qt first
        const int qt = 31 - (job >> 4), h = job & 15;
        const int gr0 = qt * 64 + m0 + g, gr1 = gr0 + 8;
        const int jmax = qt;

        // stage Q into K0 buffer (prescaled), hoist frags
        for (int idx = tid; idx < 64 * 48; idx += 128) {
            int r = idx / 48, c = idx % 48;
            float4 v = *(const float4*)(q + (size_t)((qt * 64 + r) * 16 + h) * 192 + c * 4);
            *(uint2*)(smh + r * 200 + c * 4) =
                make_uint2(pack2(v.x * QS, v.y * QS), pack2(v.z * QS, v.w * QS));
        }
        __syncthreads();
        uint32_t qf[12][4];
#pragma unroll
        for (int kk = 0; kk < 12; kk++)
            ldsm4(lmaddr(sb, m0, 200, kk * 16, lane), qf[kk][0], qf[kk][1], qf[kk][2], qf[kk][3]);
        __syncthreads();

        auto prefetch = [&](int j, int buf) {
            uint32_t kb = sb + (uint32_t)buf * 12800u * 2;
            uint32_t vb = sb + (25600u + (uint32_t)buf * 10368u) * 2;
#pragma unroll
            for (int it = 0; it < 12; it++) {
                int idx = tid + it * 128;
                int r = idx / 24, c = idx % 24;
                cp16(kb + (uint32_t)(r * 200 + c * 8) * 2,
                     g_ksp + (size_t)((j * 64 + r) * 16 + h) * 192 + c * 8);
            }
#pragma unroll
            for (int it = 0; it < 8; it++) {
                int idx = tid + it * 128;
                int r = idx >> 3, c = idx & 7;
                cp16(vb + (uint32_t)(r * 72 + c * 8) * 2,
                     g_vt + (size_t)(h * 128 + r) * 2048 + j * 64 + c * 8);
            }
        };

        prefetch(0, 0); CP_COMMIT();

        float O[16][4], Osum[4];
#pragma unroll
        for (int f = 0; f < 16; f++)
#pragma unroll
            for (int c = 0; c < 4; c++) O[f][c] = 0.f;
#pragma unroll
        for (int c = 0; c < 4; c++) Osum[c] = 0.f;
        float mr0 = -INFINITY, mr1 = -INFINITY;

        for (int j = 0; j <= jmax; j++) {
            CP_WAIT0();
            __syncthreads();   // data j ready AND all warps done reading buffer (j+1)&1 (iter j-1)
            if (j < jmax) { prefetch(j + 1, (j + 1) & 1); CP_COMMIT(); }
            const uint32_t sKb = sb + (uint32_t)(j & 1) * 12800u * 2;
            const uint32_t sVb = sb + (25600u + (uint32_t)(j & 1) * 10368u) * 2;

            // S = Q @ K^T
            float Sc[8][4];
#pragma unroll
            for (int f = 0; f < 8; f++)
#pragma unroll
                for (int c = 0; c < 4; c++) Sc[f][c] = 0.f;
#pragma unroll
            for (int kk = 0; kk < 12; kk++) {
#pragma unroll
                for (int nf2 = 0; nf2 < 4; nf2++) {
                    uint32_t b0, b1, b2, b3;
                    ldsm4(lmaddr(sKb, nf2 * 16, 200, kk * 16, lane), b0, b1, b2, b3);
                    mma16816(Sc[2 * nf2],     qf[kk][0], qf[kk][1], qf[kk][2], qf[kk][3], b0, b2);
                    mma16816(Sc[2 * nf2 + 1], qf[kk][0], qf[kk][1], qf[kk][2], qf[kk][3], b1, b3);
                }
            }

            // mask only on diagonal tile
            if (j == jmax) {
#pragma unroll
                for (int f = 0; f < 8; f++) {
                    int c0 = j * 64 + f * 8 + t2 * 2;
                    Sc[f][0] = (c0     <= gr0) ? Sc[f][0] : MASKVAL;
                    Sc[f][1] = (c0 + 1 <= gr0) ? Sc[f][1] : MASKVAL;
                    Sc[f][2] = (c0     <= gr1) ? Sc[f][2] : MASKVAL;
                    Sc[f][3] = (c0 + 1 <= gr1) ? Sc[f][3] : MASKVAL;
                }
            }
            // row max
            float mx0 = -INFINITY, mx1 = -INFINITY;
#pragma unroll
            for (int f = 0; f < 8; f++) {
                mx0 = fmaxf(mx0, fmaxf(Sc[f][0], Sc[f][1]));
                mx1 = fmaxf(mx1, fmaxf(Sc[f][2], Sc[f][3]));
            }
            mx0 = fmaxf(mx0, __shfl_xor_sync(0xffffffffu, mx0, 1));
            mx0 = fmaxf(mx0, __shfl_xor_sync(0xffffffffu, mx0, 2));
            mx1 = fmaxf(mx1, __shfl_xor_sync(0xffffffffu, mx1, 1));
            mx1 = fmaxf(mx1, __shfl_xor_sync(0xffffffffu, mx1, 2));
            float mn0 = fmaxf(mr0, mx0), mn1 = fmaxf(mr1, mx1);
            float al0 = exp2f(mr0 - mn0), al1 = exp2f(mr1 - mn1);
            mr0 = mn0; mr1 = mn1;

            if (!__all_sync(0xffffffffu, (al0 == 1.f) & (al1 == 1.f))) {
#pragma unroll
                for (int f = 0; f < 16; f++) {
                    O[f][0] *= al0; O[f][1] *= al0; O[f][2] *= al1; O[f][3] *= al1;
                }
                Osum[0] *= al0; Osum[1] *= al0; Osum[2] *= al1; Osum[3] *= al1;
            }

            uint32_t Pa[8], Pb[8];
#pragma unroll
            for (int f = 0; f < 8; f++) {
                Pa[f] = hexp2(pack2(Sc[f][0] - mn0, Sc[f][1] - mn0));
                Pb[f] = hexp2(pack2(Sc[f][2] - mn1, Sc[f][3] - mn1));
            }

            // O += P @ V  (and row-sum via ones row)
#pragma unroll
            for (int kc2 = 0; kc2 < 4; kc2++) {
                uint32_t a0 = Pa[2 * kc2], a1 = Pb[2 * kc2], a2 = Pa[2 * kc2 + 1], a3 = Pb[2 * kc2 + 1];
#pragma unroll
                for (int nf2 = 0; nf2 < 8; nf2++) {
                    uint32_t b0, b1, b2, b3;
                    ldsm4(lmaddr(sVb, nf2 * 16, 72, kc2 * 16, lane), b0, b1, b2, b3);
                    mma16816(O[2 * nf2],     a0, a1, a2, a3, b0, b2);
                    mma16816(O[2 * nf2 + 1], a0, a1, a2, a3, b1, b3);
                }
                uint32_t b0, b1, b2, b3;
                ldsm4(lmaddr(sVb, 128, 72, kc2 * 16, lane), b0, b1, b2, b3);
                mma16816(Osum, a0, a1, a2, a3, b0, b2);
            }
        }

        // epilogue
        float sum0 = __shfl_sync(0xffffffffu, Osum[0], lane & ~3);
        float sum1 = __shfl_sync(0xffffffffu, Osum[2], lane & ~3);
        float inv0 = 1.f / sum0, inv1 = 1.f / sum1;
#pragma unroll
        for (int f = 0; f < 16; f++) {
            int col = h * 128 + f * 8 + t2 * 2;
            *(float2*)(out + (size_t)gr0 * 2048 + col) = make_float2(O[f][0] * inv0, O[f][1] * inv0);
            *(float2*)(out + (size_t)gr1 * 2048 + col) = make_float2(O[f][2] * inv1, O[f][3] * inv1);
        }
        __syncthreads();   // final tile reads + output done before next job's staging
    }
}

// ---------------------------------------------------------------------------
extern "C" void kernel_launch(void* const* d_in, const int* in_sizes, int n_in,
                              void* d_out, int out_size) {
    (void)in_sizes; (void)n_in; (void)out_size;
    const float* q   = (const float*)d_in[0];
    const float* kc  = (const float*)d_in[1];
    const float* kpe = (const float*)d_in[2];
    const float* wkv = (const float*)d_in[3];
    const float* wuv = (const float*)d_in[4];
    float* out = (float*)d_out;

    conv_all<<<4608, 256>>>(wkv, wuv, kc, kpe);

    cudaFuncSetAttribute(pregemm, cudaFuncAttributeMaxDynamicSharedMemorySize, PG_SMEM);
    cudaFuncSetAttribute(attn,    cudaFuncAttributeMaxDynamicSharedMemorySize, AT_SMEM);

    pregemm<<<dim3(32, 16), 256, PG_SMEM>>>();
    attn<<<296, 128, AT_SMEM>>>(q, out);
}